// round 1
// baseline (speedup 1.0000x reference)
#include <cuda_runtime.h>
#include <cuda_bf16.h>
#include <math.h>

// Problem constants
#define S_LEN 2048
#define D_DIM 1024
#define H_NUM 16
#define HD_DIM 64
#define B_NUM 2
#define M_TOT (B_NUM * S_LEN)   // 4096

// Scratch (allocation-free rule: __device__ globals)
__device__ float g_Q[B_NUM * H_NUM * S_LEN * HD_DIM];   // [B,H,S,HD]
__device__ float g_K[B_NUM * H_NUM * S_LEN * HD_DIM];
__device__ float g_V[B_NUM * H_NUM * S_LEN * HD_DIM];
__device__ float g_Ctx[B_NUM * S_LEN * D_DIM];          // merged heads [B,S,D]

// ---------------------------------------------------------------------------
// SGEMM: C = A @ W + bias
// A: [4096, 1024] row-major, W: [1024, 1024] row-major
// mode 0: C[m*1024 + n]
// mode 1: head-split epilogue -> C[((b*H + h)*S + s)*HD + hd]
// Tiles: BM=BN=128, BK=16, 256 threads, 8x8 per thread as 2x2 fragments of 4x4
// (fragments at m/n offsets {ty*4, 64+ty*4} / {tx*4, 64+tx*4}).
// ---------------------------------------------------------------------------
__global__ __launch_bounds__(256, 2) void sgemm_kernel(
    const float* __restrict__ A, const float* __restrict__ W,
    const float* __restrict__ bias, float* __restrict__ C, int mode)
{
    __shared__ float As[16][132];   // transposed: As[k][m], pad to 132
    __shared__ float Bs[16][132];   // natural:    Bs[k][n], pad to 132

    const int tid = threadIdx.x;
    const int tx = tid & 15;
    const int ty = tid >> 4;
    const int bm = blockIdx.y << 7;
    const int bn = blockIdx.x << 7;

    float acc[2][2][4][4];
    #pragma unroll
    for (int p = 0; p < 2; p++)
        #pragma unroll
        for (int q = 0; q < 2; q++)
            #pragma unroll
            for (int i = 0; i < 4; i++)
                #pragma unroll
                for (int j = 0; j < 4; j++)
                    acc[p][q][i][j] = 0.0f;

    for (int k0 = 0; k0 < D_DIM; k0 += 16) {
        // ---- load tiles ----
        #pragma unroll
        for (int it = 0; it < 2; it++) {
            int lin = tid + it * 256;            // 0..511
            int arow = lin >> 2;                 // 0..127
            int ak   = (lin & 3) << 2;           // 0,4,8,12
            float4 av = *(const float4*)(A + (size_t)(bm + arow) * D_DIM + k0 + ak);
            As[ak + 0][arow] = av.x;
            As[ak + 1][arow] = av.y;
            As[ak + 2][arow] = av.z;
            As[ak + 3][arow] = av.w;

            int brow = lin >> 5;                 // 0..15
            int bc   = (lin & 31) << 2;          // 0..124
            *(float4*)&Bs[brow][bc] =
                *(const float4*)(W + (size_t)(k0 + brow) * D_DIM + bn + bc);
        }
        __syncthreads();

        // ---- compute ----
        #pragma unroll 8
        for (int kk = 0; kk < 16; kk++) {
            float4 a0 = *(const float4*)&As[kk][ty * 4];
            float4 a1 = *(const float4*)&As[kk][64 + ty * 4];
            float4 b0 = *(const float4*)&Bs[kk][tx * 4];
            float4 b1 = *(const float4*)&Bs[kk][64 + tx * 4];
            float af[2][4] = {{a0.x, a0.y, a0.z, a0.w}, {a1.x, a1.y, a1.z, a1.w}};
            float bf[2][4] = {{b0.x, b0.y, b0.z, b0.w}, {b1.x, b1.y, b1.z, b1.w}};
            #pragma unroll
            for (int p = 0; p < 2; p++)
                #pragma unroll
                for (int q = 0; q < 2; q++)
                    #pragma unroll
                    for (int i = 0; i < 4; i++)
                        #pragma unroll
                        for (int j = 0; j < 4; j++)
                            acc[p][q][i][j] += af[p][i] * bf[q][j];
        }
        __syncthreads();
    }

    // ---- epilogue ----
    #pragma unroll
    for (int p = 0; p < 2; p++) {
        #pragma unroll
        for (int i = 0; i < 4; i++) {
            int m = bm + p * 64 + ty * 4 + i;
            #pragma unroll
            for (int q = 0; q < 2; q++) {
                int n = bn + q * 64 + tx * 4;
                float4 r;
                r.x = acc[p][q][i][0] + bias[n + 0];
                r.y = acc[p][q][i][1] + bias[n + 1];
                r.z = acc[p][q][i][2] + bias[n + 2];
                r.w = acc[p][q][i][3] + bias[n + 3];
                if (mode == 0) {
                    *(float4*)(C + (size_t)m * D_DIM + n) = r;
                } else {
                    int b  = m >> 11;          // m / S_LEN
                    int s  = m & (S_LEN - 1);
                    int h  = n >> 6;           // n / HD
                    int hd = n & (HD_DIM - 1);
                    size_t idx = (((size_t)(b * H_NUM + h) * S_LEN + s) << 6) + hd;
                    *(float4*)(C + idx) = r;
                }
            }
        }
    }
}

// ---------------------------------------------------------------------------
// Flash attention (causal), fp32.
// Grid: (S/64 q-blocks, B*H). Block: 256 threads = 16x16.
// Each thread owns a 4x4 S-fragment: rows r = ty*4+i, cols c = tx + 16*j
// (strided cols keep Ks LDS.128 reads at the 2-phase minimum).
// smem: Qs[64][68], Ks[64][68], Vs[64][68], Pst[64][65] (P transposed, pitch 65)
// ---------------------------------------------------------------------------
#define QKV_PITCH 68
#define P_PITCH 65
#define FLASH_SMEM_BYTES ((3 * 64 * QKV_PITCH + 64 * P_PITCH) * 4)

__global__ __launch_bounds__(256, 2) void flash_kernel(
    const float* __restrict__ Q, const float* __restrict__ K,
    const float* __restrict__ V, float* __restrict__ Out)
{
    extern __shared__ float sm[];
    float* Qs  = sm;                       // 64 x 68
    float* Ks  = Qs + 64 * QKV_PITCH;      // 64 x 68
    float* Vs  = Ks + 64 * QKV_PITCH;      // 64 x 68
    float* Pst = Vs + 64 * QKV_PITCH;      // 64 x 65  (Pst[k][r])

    const int tid = threadIdx.x;
    const int tx = tid & 15;
    const int ty = tid >> 4;
    const int qb = blockIdx.x;
    const int bh = blockIdx.y;
    const int q0 = qb * 64;

    const float* Qg = Q + ((size_t)bh * S_LEN + q0) * HD_DIM;

    // load Q tile [64 x 64]
    #pragma unroll
    for (int it = 0; it < 4; it++) {
        int lin = tid + it * 256;          // 0..1023
        int row = lin >> 4;                // 0..63
        int d4  = (lin & 15) << 2;         // 0..60
        *(float4*)&Qs[row * QKV_PITCH + d4] =
            *(const float4*)&Qg[row * HD_DIM + d4];
    }

    float m_i[4], l_i[4], o[4][4];
    #pragma unroll
    for (int i = 0; i < 4; i++) {
        m_i[i] = -1e30f;
        l_i[i] = 0.0f;
        #pragma unroll
        for (int j = 0; j < 4; j++) o[i][j] = 0.0f;
    }

    for (int t = 0; t <= qb; t++) {
        __syncthreads();   // previous iteration's PV done; Qs stores visible

        // load K,V tiles for kv rows [t*64, t*64+63]
        const float* Kg = K + ((size_t)bh * S_LEN + t * 64) * HD_DIM;
        const float* Vg = V + ((size_t)bh * S_LEN + t * 64) * HD_DIM;
        #pragma unroll
        for (int it = 0; it < 4; it++) {
            int lin = tid + it * 256;
            int row = lin >> 4;
            int d4  = (lin & 15) << 2;
            *(float4*)&Ks[row * QKV_PITCH + d4] =
                *(const float4*)&Kg[row * HD_DIM + d4];
            *(float4*)&Vs[row * QKV_PITCH + d4] =
                *(const float4*)&Vg[row * HD_DIM + d4];
        }
        __syncthreads();

        // ---- S = Q K^T (4x4 fragment per thread), float4 dot along d ----
        float s[4][4];
        #pragma unroll
        for (int i = 0; i < 4; i++)
            #pragma unroll
            for (int j = 0; j < 4; j++) s[i][j] = 0.0f;

        #pragma unroll 4
        for (int d4 = 0; d4 < HD_DIM; d4 += 4) {
            float4 qv[4], kv[4];
            #pragma unroll
            for (int i = 0; i < 4; i++)
                qv[i] = *(const float4*)&Qs[(ty * 4 + i) * QKV_PITCH + d4];
            #pragma unroll
            for (int j = 0; j < 4; j++)
                kv[j] = *(const float4*)&Ks[(tx + 16 * j) * QKV_PITCH + d4];
            #pragma unroll
            for (int i = 0; i < 4; i++)
                #pragma unroll
                for (int j = 0; j < 4; j++) {
                    s[i][j] += qv[i].x * kv[j].x;
                    s[i][j] += qv[i].y * kv[j].y;
                    s[i][j] += qv[i].z * kv[j].z;
                    s[i][j] += qv[i].w * kv[j].w;
                }
        }

        // ---- scale + causal mask ----
        const bool diag = (t == qb);
        #pragma unroll
        for (int i = 0; i < 4; i++)
            #pragma unroll
            for (int j = 0; j < 4; j++) {
                float v = s[i][j] * 0.125f;   // 1/sqrt(64)
                if (diag && (tx + 16 * j) > (ty * 4 + i)) v -= 1.0e9f;
                s[i][j] = v;
            }

        // ---- online softmax ----
        #pragma unroll
        for (int i = 0; i < 4; i++) {
            float rm = fmaxf(fmaxf(s[i][0], s[i][1]), fmaxf(s[i][2], s[i][3]));
            #pragma unroll
            for (int off = 8; off >= 1; off >>= 1)
                rm = fmaxf(rm, __shfl_xor_sync(0xffffffffu, rm, off, 16));
            float mn = fmaxf(m_i[i], rm);
            float factor = __expf(m_i[i] - mn);
            m_i[i] = mn;

            float rs = 0.0f;
            #pragma unroll
            for (int j = 0; j < 4; j++) {
                float p = __expf(s[i][j] - mn);
                s[i][j] = p;
                rs += p;
            }
            #pragma unroll
            for (int off = 8; off >= 1; off >>= 1)
                rs += __shfl_xor_sync(0xffffffffu, rs, off, 16);
            l_i[i] = l_i[i] * factor + rs;

            #pragma unroll
            for (int j = 0; j < 4; j++) o[i][j] *= factor;
        }

        // ---- exchange P through smem (transposed, pitch 65) ----
        #pragma unroll
        for (int i = 0; i < 4; i++)
            #pragma unroll
            for (int j = 0; j < 4; j++)
                Pst[(tx + 16 * j) * P_PITCH + ty * 4 + i] = s[i][j];
        __syncthreads();

        // ---- O += P @ V (outer product over k) ----
        #pragma unroll 8
        for (int k = 0; k < 64; k++) {
            float pv[4], vv[4];
            #pragma unroll
            for (int i = 0; i < 4; i++)
                pv[i] = Pst[k * P_PITCH + ty * 4 + i];
            #pragma unroll
            for (int j = 0; j < 4; j++)
                vv[j] = Vs[k * QKV_PITCH + tx + 16 * j];
            #pragma unroll
            for (int i = 0; i < 4; i++)
                #pragma unroll
                for (int j = 0; j < 4; j++)
                    o[i][j] += pv[i] * vv[j];
        }
    }

    // ---- write merged-head output [B, S, D] ----
    const int b = bh >> 4;          // bh / H
    const int h = bh & 15;
    #pragma unroll
    for (int i = 0; i < 4; i++) {
        float inv_l = 1.0f / l_i[i];
        size_t rowbase = ((size_t)b * S_LEN + q0 + ty * 4 + i) * D_DIM + h * HD_DIM;
        #pragma unroll
        for (int j = 0; j < 4; j++)
            Out[rowbase + tx + 16 * j] = o[i][j] * inv_l;
    }
}

// ---------------------------------------------------------------------------
// Launch
// ---------------------------------------------------------------------------
extern "C" void kernel_launch(void* const* d_in, const int* in_sizes, int n_in,
                              void* d_out, int out_size)
{
    const float* x  = (const float*)d_in[0];
    // d_in[1] = mask (causal triu * 1) — reproduced analytically in-kernel
    const float* wq = (const float*)d_in[2];
    const float* bq = (const float*)d_in[3];
    const float* wk = (const float*)d_in[4];
    const float* bk = (const float*)d_in[5];
    const float* wv = (const float*)d_in[6];
    const float* bv = (const float*)d_in[7];
    const float* wo = (const float*)d_in[8];
    const float* bo = (const float*)d_in[9];
    float* out = (float*)d_out;

    float *Qp, *Kp, *Vp, *Cp;
    cudaGetSymbolAddress((void**)&Qp, g_Q);
    cudaGetSymbolAddress((void**)&Kp, g_K);
    cudaGetSymbolAddress((void**)&Vp, g_V);
    cudaGetSymbolAddress((void**)&Cp, g_Ctx);

    cudaFuncSetAttribute(flash_kernel,
                         cudaFuncAttributeMaxDynamicSharedMemorySize,
                         FLASH_SMEM_BYTES);

    dim3 gemm_grid(D_DIM / 128, M_TOT / 128);   // (8, 32)
    sgemm_kernel<<<gemm_grid, 256>>>(x, wq, bq, Qp, 1);
    sgemm_kernel<<<gemm_grid, 256>>>(x, wk, bk, Kp, 1);
    sgemm_kernel<<<gemm_grid, 256>>>(x, wv, bv, Vp, 1);

    flash_kernel<<<dim3(S_LEN / 64, B_NUM * H_NUM), 256, FLASH_SMEM_BYTES>>>(
        Qp, Kp, Vp, Cp);

    sgemm_kernel<<<gemm_grid, 256>>>(Cp, wo, bo, out, 0);
}

// round 3
// speedup vs baseline: 1.7233x; 1.7233x over previous
#include <cuda_runtime.h>
#include <cuda_bf16.h>
#include <cstdint>
#include <math.h>

// Problem constants
#define S_LEN 2048
#define D_DIM 1024
#define H_NUM 16
#define HD_DIM 64
#define B_NUM 2
#define M_TOT (B_NUM * S_LEN)   // 4096
#define N_QKV (3 * D_DIM)       // 3072

// Scratch (allocation-free rule: __device__ globals)
__device__ float g_Q[B_NUM * H_NUM * S_LEN * HD_DIM];   // [B,H,S,HD]
__device__ float g_K[B_NUM * H_NUM * S_LEN * HD_DIM];
__device__ float g_V[B_NUM * H_NUM * S_LEN * HD_DIM];
__device__ float g_Ctx[B_NUM * S_LEN * D_DIM];          // merged heads [B,S,D], tf32-rounded
__device__ float g_xc[M_TOT * D_DIM];                   // x, tf32-rounded
__device__ float g_WT[4 * D_DIM * D_DIM];               // [4096 n][1024 k] K-major, tf32-rounded

// ===========================================================================
// Helpers
// ===========================================================================
__device__ __forceinline__ uint32_t smem_to_u32(const void* smem_ptr) {
    uint32_t addr;
    asm("{ .reg .u64 tmp; cvta.to.shared.u64 tmp, %1; cvt.u32.u64 %0, tmp; }"
        : "=r"(addr) : "l"(smem_ptr));
    return addr;
}
__device__ __forceinline__ float cvt_rna_tf32(float x) {
    uint32_t r;
    asm("cvt.rna.tf32.f32 %0, %1;" : "=r"(r) : "f"(x));
    return __uint_as_float(r);
}
#define CP_ASYNC16(smem_u32, gptr) \
    asm volatile("cp.async.cg.shared.global [%0], [%1], 16;" \
        :: "r"(smem_u32), "l"(gptr) : "memory")
#define CP_COMMIT() asm volatile("cp.async.commit_group;" ::: "memory")
#define CP_WAIT0()  asm volatile("cp.async.wait_group 0;" ::: "memory")

// m16n8k8 tf32 MMA, accumulate in registers.
__device__ __forceinline__ void mma_tf32(float* d, const uint32_t* a, const uint32_t* b) {
    asm volatile(
        "mma.sync.aligned.m16n8k8.row.col.f32.tf32.tf32.f32 "
        "{%0,%1,%2,%3}, {%4,%5,%6,%7}, {%8,%9}, {%0,%1,%2,%3};"
        : "+f"(d[0]), "+f"(d[1]), "+f"(d[2]), "+f"(d[3])
        : "r"(a[0]), "r"(a[1]), "r"(a[2]), "r"(a[3]), "r"(b[0]), "r"(b[1]));
}

// ===========================================================================
// cvt kernel: round x to tf32 (rna) into g_xc
// ===========================================================================
__global__ void cvt_x_kernel(const float* __restrict__ in, float* __restrict__ out)
{
    int i = blockIdx.x * blockDim.x + threadIdx.x;   // over float4s
    float4 v = ((const float4*)in)[i];
    v.x = cvt_rna_tf32(v.x); v.y = cvt_rna_tf32(v.y);
    v.z = cvt_rna_tf32(v.z); v.w = cvt_rna_tf32(v.w);
    ((float4*)out)[i] = v;
}

// ===========================================================================
// Weight transpose + tf32 round: W[k][n] -> WT[n][k], 4 matrices concatenated
// ===========================================================================
__global__ void transpose_w_kernel(
    const float* __restrict__ wq, const float* __restrict__ wk,
    const float* __restrict__ wv, const float* __restrict__ wo,
    float* __restrict__ WT)
{
    __shared__ float t[32][33];
    const int tx = threadIdx.x & 31;
    const int ty = threadIdx.x >> 5;    // 0..7
    const int x = blockIdx.x * 32;      // k tile
    const int y = blockIdx.y * 32;      // n tile (global, 0..4095)
    const int seg = y >> 10;
    const float* W = (seg == 0) ? wq : (seg == 1) ? wk : (seg == 2) ? wv : wo;
    const int d0 = y & 1023;
    #pragma unroll
    for (int i = 0; i < 4; i++)
        t[ty + i * 8][tx] = W[(size_t)(x + ty + i * 8) * D_DIM + d0 + tx];
    __syncthreads();
    #pragma unroll
    for (int i = 0; i < 4; i++)
        WT[(size_t)(y + ty + i * 8) * D_DIM + x + tx] = cvt_rna_tf32(t[tx][ty + i * 8]);
}

// ===========================================================================
// tf32 mma.sync GEMM: C[M_TOT x N] = A @ WT^T + bias
// A: [M_TOT][1024] K-major tf32, WT: [N][1024] K-major tf32
// CTA tile 128x128, BK=32, 256 threads. 8 warps = 4(m) x 2(n).
// Warp tile 32x64 = 2 x 8 m16n8k8 tiles.
// smem: As/Bs [2 stages][128 rows][36 pitch] fp32, cp.async double-buffered.
// Fragment LDS: addr = row*36 + k  ->  bank = (4*row + k) & 31, conflict-free.
// mode 0: plain C[m*1024+n] (O projection, bias b0)
// mode 1: QKV fused (N=3072): head-split epilogue into out0/out1/out2
// ===========================================================================
#define GPITCH 36
#define STAGE_FLOATS (128 * GPITCH)                    // per matrix per stage
#define GEMM_SMEM_BYTES (4 * STAGE_FLOATS * 4)         // 2 matrices x 2 stages = 73728

__global__ __launch_bounds__(256, 2) void gemm_mma_kernel(
    const float* __restrict__ A, const float* __restrict__ WT,
    const float* __restrict__ b0, const float* __restrict__ b1, const float* __restrict__ b2,
    float* __restrict__ out0, float* __restrict__ out1, float* __restrict__ out2,
    int mode)
{
    extern __shared__ float sm[];
    float* As = sm;                          // [2][128][36]
    float* Bs = sm + 2 * STAGE_FLOATS;       // [2][128][36]
    const uint32_t as_u32 = smem_to_u32(As);
    const uint32_t bs_u32 = smem_to_u32(Bs);

    const int tid  = threadIdx.x;
    const int wid  = tid >> 5;
    const int lane = tid & 31;
    const int bm = blockIdx.y << 7;
    const int bn = blockIdx.x << 7;
    const int wm = (wid & 3) << 5;     // warp m offset (0,32,64,96)
    const int wn = (wid >> 2) << 6;    // warp n offset (0,64)

    float acc[2][8][4];
    #pragma unroll
    for (int i = 0; i < 2; i++)
        #pragma unroll
        for (int j = 0; j < 8; j++)
            #pragma unroll
            for (int e = 0; e < 4; e++) acc[i][j][e] = 0.0f;

    // thread's cp.async slice: 4 float4 per matrix per stage
    const int ldrow = tid >> 3;          // 0..31 step: f>>3 with f=tid+it*256
    const int ldk   = (tid & 7) << 2;    // 0,4,...,28

    // ---- prologue: stage 0 ----
    #pragma unroll
    for (int it = 0; it < 4; it++) {
        int row = ldrow + it * 32;
        CP_ASYNC16(as_u32 + (row * GPITCH + ldk) * 4,
                   A + (size_t)(bm + row) * D_DIM + ldk);
        CP_ASYNC16(bs_u32 + (row * GPITCH + ldk) * 4,
                   WT + (size_t)(bn + row) * D_DIM + ldk);
    }
    CP_COMMIT();
    CP_WAIT0();
    __syncthreads();

    const int fr = lane >> 2;    // 0..7
    const int fc = lane & 3;     // 0..3

    for (int kt = 0; kt < D_DIM / 32; kt++) {
        const int buf = kt & 1;

        if (kt + 1 < D_DIM / 32) {
            const int k0 = (kt + 1) << 5;
            const uint32_t adst = as_u32 + ((buf ^ 1) * STAGE_FLOATS) * 4;
            const uint32_t bdst = bs_u32 + ((buf ^ 1) * STAGE_FLOATS) * 4;
            #pragma unroll
            for (int it = 0; it < 4; it++) {
                int row = ldrow + it * 32;
                CP_ASYNC16(adst + (row * GPITCH + ldk) * 4,
                           A + (size_t)(bm + row) * D_DIM + k0 + ldk);
                CP_ASYNC16(bdst + (row * GPITCH + ldk) * 4,
                           WT + (size_t)(bn + row) * D_DIM + k0 + ldk);
            }
            CP_COMMIT();
        }

        const float* Ab = As + buf * STAGE_FLOATS;
        const float* Bb = Bs + buf * STAGE_FLOATS;

        #pragma unroll
        for (int ks = 0; ks < 4; ks++) {
            const int k8 = ks << 3;
            uint32_t af[2][4], bf[8][2];
            #pragma unroll
            for (int i = 0; i < 2; i++) {
                const int m0 = wm + i * 16;
                af[i][0] = __float_as_uint(Ab[(m0 + fr)     * GPITCH + k8 + fc]);
                af[i][1] = __float_as_uint(Ab[(m0 + fr + 8) * GPITCH + k8 + fc]);
                af[i][2] = __float_as_uint(Ab[(m0 + fr)     * GPITCH + k8 + fc + 4]);
                af[i][3] = __float_as_uint(Ab[(m0 + fr + 8) * GPITCH + k8 + fc + 4]);
            }
            #pragma unroll
            for (int j = 0; j < 8; j++) {
                const int n0 = wn + j * 8;
                bf[j][0] = __float_as_uint(Bb[(n0 + fr) * GPITCH + k8 + fc]);
                bf[j][1] = __float_as_uint(Bb[(n0 + fr) * GPITCH + k8 + fc + 4]);
            }
            #pragma unroll
            for (int i = 0; i < 2; i++)
                #pragma unroll
                for (int j = 0; j < 8; j++)
                    mma_tf32(acc[i][j], af[i], bf[j]);
        }

        if (kt + 1 < D_DIM / 32) CP_WAIT0();
        __syncthreads();
    }

    // ---- epilogue ----
    const int c2 = (lane & 3) << 1;
    #pragma unroll
    for (int i = 0; i < 2; i++) {
        #pragma unroll
        for (int rr = 0; rr < 2; rr++) {
            const int m = bm + wm + i * 16 + fr + rr * 8;
            const int b = m >> 11;
            const int s = m & (S_LEN - 1);
            #pragma unroll
            for (int j = 0; j < 8; j++) {
                const int n = bn + wn + j * 8 + c2;
                float v0 = acc[i][j][rr * 2 + 0];
                float v1 = acc[i][j][rr * 2 + 1];
                if (mode == 0) {
                    float2 w;
                    w.x = v0 + b0[n + 0];
                    w.y = v1 + b0[n + 1];
                    *(float2*)(out0 + (size_t)m * D_DIM + n) = w;
                } else {
                    const int seg = n >> 10;
                    const int d = n & 1023;
                    const float* bp = (seg == 0) ? b0 : (seg == 1) ? b1 : b2;
                    float* op = (seg == 0) ? out0 : (seg == 1) ? out1 : out2;
                    const int h = d >> 6;
                    const int hd = d & 63;
                    float2 w;
                    w.x = v0 + bp[d + 0];
                    w.y = v1 + bp[d + 1];
                    size_t idx = ((((size_t)(b * H_NUM + h)) << 11) + s) * HD_DIM + hd;
                    *(float2*)(op + idx) = w;
                }
            }
        }
    }
}

// ---------------------------------------------------------------------------
// Flash attention (causal), fp32 — unchanged; tf32-rounds its output for the
// O-projection MMA.
// ---------------------------------------------------------------------------
#define QKV_PITCH 68
#define P_PITCH 65
#define FLASH_SMEM_BYTES ((3 * 64 * QKV_PITCH + 64 * P_PITCH) * 4)

__global__ __launch_bounds__(256, 2) void flash_kernel(
    const float* __restrict__ Q, const float* __restrict__ K,
    const float* __restrict__ V, float* __restrict__ Out)
{
    extern __shared__ float smf[];
    float* Qs  = smf;
    float* Ks  = Qs + 64 * QKV_PITCH;
    float* Vs  = Ks + 64 * QKV_PITCH;
    float* Pst = Vs + 64 * QKV_PITCH;

    const int tid = threadIdx.x;
    const int tx = tid & 15;
    const int ty = tid >> 4;
    const int qb = blockIdx.x;
    const int bh = blockIdx.y;
    const int q0 = qb * 64;

    const float* Qg = Q + ((size_t)bh * S_LEN + q0) * HD_DIM;

    #pragma unroll
    for (int it = 0; it < 4; it++) {
        int lin = tid + it * 256;
        int row = lin >> 4;
        int d4  = (lin & 15) << 2;
        *(float4*)&Qs[row * QKV_PITCH + d4] =
            *(const float4*)&Qg[row * HD_DIM + d4];
    }

    float m_i[4], l_i[4], o[4][4];
    #pragma unroll
    for (int i = 0; i < 4; i++) {
        m_i[i] = -1e30f;
        l_i[i] = 0.0f;
        #pragma unroll
        for (int j = 0; j < 4; j++) o[i][j] = 0.0f;
    }

    for (int t = 0; t <= qb; t++) {
        __syncthreads();

        const float* Kg = K + ((size_t)bh * S_LEN + t * 64) * HD_DIM;
        const float* Vg = V + ((size_t)bh * S_LEN + t * 64) * HD_DIM;
        #pragma unroll
        for (int it = 0; it < 4; it++) {
            int lin = tid + it * 256;
            int row = lin >> 4;
            int d4  = (lin & 15) << 2;
            *(float4*)&Ks[row * QKV_PITCH + d4] =
                *(const float4*)&Kg[row * HD_DIM + d4];
            *(float4*)&Vs[row * QKV_PITCH + d4] =
                *(const float4*)&Vg[row * HD_DIM + d4];
        }
        __syncthreads();

        float s[4][4];
        #pragma unroll
        for (int i = 0; i < 4; i++)
            #pragma unroll
            for (int j = 0; j < 4; j++) s[i][j] = 0.0f;

        #pragma unroll 4
        for (int d4 = 0; d4 < HD_DIM; d4 += 4) {
            float4 qv[4], kv[4];
            #pragma unroll
            for (int i = 0; i < 4; i++)
                qv[i] = *(const float4*)&Qs[(ty * 4 + i) * QKV_PITCH + d4];
            #pragma unroll
            for (int j = 0; j < 4; j++)
                kv[j] = *(const float4*)&Ks[(tx + 16 * j) * QKV_PITCH + d4];
            #pragma unroll
            for (int i = 0; i < 4; i++)
                #pragma unroll
                for (int j = 0; j < 4; j++) {
                    s[i][j] += qv[i].x * kv[j].x;
                    s[i][j] += qv[i].y * kv[j].y;
                    s[i][j] += qv[i].z * kv[j].z;
                    s[i][j] += qv[i].w * kv[j].w;
                }
        }

        const bool diag = (t == qb);
        #pragma unroll
        for (int i = 0; i < 4; i++)
            #pragma unroll
            for (int j = 0; j < 4; j++) {
                float v = s[i][j] * 0.125f;
                if (diag && (tx + 16 * j) > (ty * 4 + i)) v -= 1.0e9f;
                s[i][j] = v;
            }

        #pragma unroll
        for (int i = 0; i < 4; i++) {
            float rm = fmaxf(fmaxf(s[i][0], s[i][1]), fmaxf(s[i][2], s[i][3]));
            #pragma unroll
            for (int off = 8; off >= 1; off >>= 1)
                rm = fmaxf(rm, __shfl_xor_sync(0xffffffffu, rm, off, 16));
            float mn = fmaxf(m_i[i], rm);
            float factor = __expf(m_i[i] - mn);
            m_i[i] = mn;

            float rs = 0.0f;
            #pragma unroll
            for (int j = 0; j < 4; j++) {
                float p = __expf(s[i][j] - mn);
                s[i][j] = p;
                rs += p;
            }
            #pragma unroll
            for (int off = 8; off >= 1; off >>= 1)
                rs += __shfl_xor_sync(0xffffffffu, rs, off, 16);
            l_i[i] = l_i[i] * factor + rs;

            #pragma unroll
            for (int j = 0; j < 4; j++) o[i][j] *= factor;
        }

        #pragma unroll
        for (int i = 0; i < 4; i++)
            #pragma unroll
            for (int j = 0; j < 4; j++)
                Pst[(tx + 16 * j) * P_PITCH + ty * 4 + i] = s[i][j];
        __syncthreads();

        #pragma unroll 8
        for (int k = 0; k < 64; k++) {
            float pv[4], vv[4];
            #pragma unroll
            for (int i = 0; i < 4; i++)
                pv[i] = Pst[k * P_PITCH + ty * 4 + i];
            #pragma unroll
            for (int j = 0; j < 4; j++)
                vv[j] = Vs[k * QKV_PITCH + tx + 16 * j];
            #pragma unroll
            for (int i = 0; i < 4; i++)
                #pragma unroll
                for (int j = 0; j < 4; j++)
                    o[i][j] += pv[i] * vv[j];
        }
    }

    const int b = bh >> 4;
    const int h = bh & 15;
    #pragma unroll
    for (int i = 0; i < 4; i++) {
        float inv_l = 1.0f / l_i[i];
        size_t rowbase = ((size_t)b * S_LEN + q0 + ty * 4 + i) * D_DIM + h * HD_DIM;
        #pragma unroll
        for (int j = 0; j < 4; j++)
            Out[rowbase + tx + 16 * j] = cvt_rna_tf32(o[i][j] * inv_l);
    }
}

// ---------------------------------------------------------------------------
// Launch
// ---------------------------------------------------------------------------
extern "C" void kernel_launch(void* const* d_in, const int* in_sizes, int n_in,
                              void* d_out, int out_size)
{
    const float* x  = (const float*)d_in[0];
    // d_in[1] = mask — reproduced analytically in-kernel
    const float* wq = (const float*)d_in[2];
    const float* bq = (const float*)d_in[3];
    const float* wk = (const float*)d_in[4];
    const float* bk = (const float*)d_in[5];
    const float* wv = (const float*)d_in[6];
    const float* bv = (const float*)d_in[7];
    const float* wo = (const float*)d_in[8];
    const float* bo = (const float*)d_in[9];
    float* out = (float*)d_out;

    float *Qp, *Kp, *Vp, *Cp, *xcp, *wtp;
    cudaGetSymbolAddress((void**)&Qp, g_Q);
    cudaGetSymbolAddress((void**)&Kp, g_K);
    cudaGetSymbolAddress((void**)&Vp, g_V);
    cudaGetSymbolAddress((void**)&Cp, g_Ctx);
    cudaGetSymbolAddress((void**)&xcp, g_xc);
    cudaGetSymbolAddress((void**)&wtp, g_WT);

    cudaFuncSetAttribute(flash_kernel,
                         cudaFuncAttributeMaxDynamicSharedMemorySize,
                         FLASH_SMEM_BYTES);
    cudaFuncSetAttribute(gemm_mma_kernel,
                         cudaFuncAttributeMaxDynamicSharedMemorySize,
                         GEMM_SMEM_BYTES);

    // 1. tf32-round x
    cvt_x_kernel<<<(M_TOT * D_DIM) / (4 * 256), 256>>>(x, xcp);

    // 2. transpose + tf32-round weights (Wq|Wk|Wv|Wo -> WT[n][k])
    transpose_w_kernel<<<dim3(D_DIM / 32, (4 * D_DIM) / 32), 256>>>(wq, wk, wv, wo, wtp);

    // 3. fused QKV projection (N=3072), head-split epilogue
    gemm_mma_kernel<<<dim3(N_QKV / 128, M_TOT / 128), 256, GEMM_SMEM_BYTES>>>(
        xcp, wtp, bq, bk, bv, Qp, Kp, Vp, 1);

    // 4. attention
    flash_kernel<<<dim3(S_LEN / 64, B_NUM * H_NUM), 256, FLASH_SMEM_BYTES>>>(
        Qp, Kp, Vp, Cp);

    // 5. output projection
    gemm_mma_kernel<<<dim3(D_DIM / 128, M_TOT / 128), 256, GEMM_SMEM_BYTES>>>(
        Cp, wtp + (size_t)3 * D_DIM * D_DIM, bo, bo, bo, out, out, out, 0);
}

// round 4
// speedup vs baseline: 3.0530x; 1.7717x over previous
#include <cuda_runtime.h>
#include <cuda_bf16.h>
#include <cstdint>
#include <math.h>

// Problem constants
#define S_LEN 2048
#define D_DIM 1024
#define H_NUM 16
#define HD_DIM 64
#define B_NUM 2
#define M_TOT (B_NUM * S_LEN)   // 4096
#define N_QKV (3 * D_DIM)       // 3072

// Scratch (allocation-free rule: __device__ globals)
__device__ float g_Q[B_NUM * H_NUM * S_LEN * HD_DIM];   // [B,H,S,HD] tf32-rounded
__device__ float g_K[B_NUM * H_NUM * S_LEN * HD_DIM];
__device__ float g_V[B_NUM * H_NUM * S_LEN * HD_DIM];
__device__ float g_Ctx[B_NUM * S_LEN * D_DIM];          // merged heads [B,S,D], tf32-rounded
__device__ float g_xc[M_TOT * D_DIM];                   // x, tf32-rounded
__device__ float g_WT[4 * D_DIM * D_DIM];               // [4096 n][1024 k] K-major, tf32-rounded

// ===========================================================================
// Helpers
// ===========================================================================
__device__ __forceinline__ uint32_t smem_to_u32(const void* smem_ptr) {
    uint32_t addr;
    asm("{ .reg .u64 tmp; cvta.to.shared.u64 tmp, %1; cvt.u32.u64 %0, tmp; }"
        : "=r"(addr) : "l"(smem_ptr));
    return addr;
}
__device__ __forceinline__ float cvt_rna_tf32(float x) {
    uint32_t r;
    asm("cvt.rna.tf32.f32 %0, %1;" : "=r"(r) : "f"(x));
    return __uint_as_float(r);
}
#define CP_ASYNC16(smem_u32, gptr) \
    asm volatile("cp.async.cg.shared.global [%0], [%1], 16;" \
        :: "r"(smem_u32), "l"(gptr) : "memory")
#define CP_COMMIT() asm volatile("cp.async.commit_group;" ::: "memory")
#define CP_WAIT0()  asm volatile("cp.async.wait_group 0;" ::: "memory")

// m16n8k8 tf32 MMA, accumulate in registers.
__device__ __forceinline__ void mma_tf32(float* d, const uint32_t* a, const uint32_t* b) {
    asm volatile(
        "mma.sync.aligned.m16n8k8.row.col.f32.tf32.tf32.f32 "
        "{%0,%1,%2,%3}, {%4,%5,%6,%7}, {%8,%9}, {%0,%1,%2,%3};"
        : "+f"(d[0]), "+f"(d[1]), "+f"(d[2]), "+f"(d[3])
        : "r"(a[0]), "r"(a[1]), "r"(a[2]), "r"(a[3]), "r"(b[0]), "r"(b[1]));
}

// ===========================================================================
// cvt kernel: round x to tf32 (rna) into g_xc
// ===========================================================================
__global__ void cvt_x_kernel(const float* __restrict__ in, float* __restrict__ out)
{
    int i = blockIdx.x * blockDim.x + threadIdx.x;   // over float4s
    float4 v = ((const float4*)in)[i];
    v.x = cvt_rna_tf32(v.x); v.y = cvt_rna_tf32(v.y);
    v.z = cvt_rna_tf32(v.z); v.w = cvt_rna_tf32(v.w);
    ((float4*)out)[i] = v;
}

// ===========================================================================
// Weight transpose + tf32 round: W[k][n] -> WT[n][k], 4 matrices concatenated
// ===========================================================================
__global__ void transpose_w_kernel(
    const float* __restrict__ wq, const float* __restrict__ wk,
    const float* __restrict__ wv, const float* __restrict__ wo,
    float* __restrict__ WT)
{
    __shared__ float t[32][33];
    const int tx = threadIdx.x & 31;
    const int ty = threadIdx.x >> 5;    // 0..7
    const int x = blockIdx.x * 32;      // k tile
    const int y = blockIdx.y * 32;      // n tile (global, 0..4095)
    const int seg = y >> 10;
    const float* W = (seg == 0) ? wq : (seg == 1) ? wk : (seg == 2) ? wv : wo;
    const int d0 = y & 1023;
    #pragma unroll
    for (int i = 0; i < 4; i++)
        t[ty + i * 8][tx] = W[(size_t)(x + ty + i * 8) * D_DIM + d0 + tx];
    __syncthreads();
    #pragma unroll
    for (int i = 0; i < 4; i++)
        WT[(size_t)(y + ty + i * 8) * D_DIM + x + tx] = cvt_rna_tf32(t[tx][ty + i * 8]);
}

// ===========================================================================
// tf32 mma.sync GEMM (unchanged from round 3 except mode-1 epilogue rounds
// its outputs to tf32 so flash can consume them directly).
// ===========================================================================
#define GPITCH 36
#define STAGE_FLOATS (128 * GPITCH)
#define GEMM_SMEM_BYTES (4 * STAGE_FLOATS * 4)

__global__ __launch_bounds__(256, 2) void gemm_mma_kernel(
    const float* __restrict__ A, const float* __restrict__ WT,
    const float* __restrict__ b0, const float* __restrict__ b1, const float* __restrict__ b2,
    float* __restrict__ out0, float* __restrict__ out1, float* __restrict__ out2,
    int mode)
{
    extern __shared__ float sm[];
    float* As = sm;
    float* Bs = sm + 2 * STAGE_FLOATS;
    const uint32_t as_u32 = smem_to_u32(As);
    const uint32_t bs_u32 = smem_to_u32(Bs);

    const int tid  = threadIdx.x;
    const int wid  = tid >> 5;
    const int lane = tid & 31;
    const int bm = blockIdx.y << 7;
    const int bn = blockIdx.x << 7;
    const int wm = (wid & 3) << 5;
    const int wn = (wid >> 2) << 6;

    float acc[2][8][4];
    #pragma unroll
    for (int i = 0; i < 2; i++)
        #pragma unroll
        for (int j = 0; j < 8; j++)
            #pragma unroll
            for (int e = 0; e < 4; e++) acc[i][j][e] = 0.0f;

    const int ldrow = tid >> 3;
    const int ldk   = (tid & 7) << 2;

    #pragma unroll
    for (int it = 0; it < 4; it++) {
        int row = ldrow + it * 32;
        CP_ASYNC16(as_u32 + (row * GPITCH + ldk) * 4,
                   A + (size_t)(bm + row) * D_DIM + ldk);
        CP_ASYNC16(bs_u32 + (row * GPITCH + ldk) * 4,
                   WT + (size_t)(bn + row) * D_DIM + ldk);
    }
    CP_COMMIT();
    CP_WAIT0();
    __syncthreads();

    const int fr = lane >> 2;
    const int fc = lane & 3;

    for (int kt = 0; kt < D_DIM / 32; kt++) {
        const int buf = kt & 1;

        if (kt + 1 < D_DIM / 32) {
            const int k0 = (kt + 1) << 5;
            const uint32_t adst = as_u32 + ((buf ^ 1) * STAGE_FLOATS) * 4;
            const uint32_t bdst = bs_u32 + ((buf ^ 1) * STAGE_FLOATS) * 4;
            #pragma unroll
            for (int it = 0; it < 4; it++) {
                int row = ldrow + it * 32;
                CP_ASYNC16(adst + (row * GPITCH + ldk) * 4,
                           A + (size_t)(bm + row) * D_DIM + k0 + ldk);
                CP_ASYNC16(bdst + (row * GPITCH + ldk) * 4,
                           WT + (size_t)(bn + row) * D_DIM + k0 + ldk);
            }
            CP_COMMIT();
        }

        const float* Ab = As + buf * STAGE_FLOATS;
        const float* Bb = Bs + buf * STAGE_FLOATS;

        #pragma unroll
        for (int ks = 0; ks < 4; ks++) {
            const int k8 = ks << 3;
            uint32_t af[2][4], bf[8][2];
            #pragma unroll
            for (int i = 0; i < 2; i++) {
                const int m0 = wm + i * 16;
                af[i][0] = __float_as_uint(Ab[(m0 + fr)     * GPITCH + k8 + fc]);
                af[i][1] = __float_as_uint(Ab[(m0 + fr + 8) * GPITCH + k8 + fc]);
                af[i][2] = __float_as_uint(Ab[(m0 + fr)     * GPITCH + k8 + fc + 4]);
                af[i][3] = __float_as_uint(Ab[(m0 + fr + 8) * GPITCH + k8 + fc + 4]);
            }
            #pragma unroll
            for (int j = 0; j < 8; j++) {
                const int n0 = wn + j * 8;
                bf[j][0] = __float_as_uint(Bb[(n0 + fr) * GPITCH + k8 + fc]);
                bf[j][1] = __float_as_uint(Bb[(n0 + fr) * GPITCH + k8 + fc + 4]);
            }
            #pragma unroll
            for (int i = 0; i < 2; i++)
                #pragma unroll
                for (int j = 0; j < 8; j++)
                    mma_tf32(acc[i][j], af[i], bf[j]);
        }

        if (kt + 1 < D_DIM / 32) CP_WAIT0();
        __syncthreads();
    }

    const int c2 = (lane & 3) << 1;
    #pragma unroll
    for (int i = 0; i < 2; i++) {
        #pragma unroll
        for (int rr = 0; rr < 2; rr++) {
            const int m = bm + wm + i * 16 + fr + rr * 8;
            const int b = m >> 11;
            const int s = m & (S_LEN - 1);
            #pragma unroll
            for (int j = 0; j < 8; j++) {
                const int n = bn + wn + j * 8 + c2;
                float v0 = acc[i][j][rr * 2 + 0];
                float v1 = acc[i][j][rr * 2 + 1];
                if (mode == 0) {
                    float2 w;
                    w.x = v0 + b0[n + 0];
                    w.y = v1 + b0[n + 1];
                    *(float2*)(out0 + (size_t)m * D_DIM + n) = w;
                } else {
                    const int seg = n >> 10;
                    const int d = n & 1023;
                    const float* bp = (seg == 0) ? b0 : (seg == 1) ? b1 : b2;
                    float* op = (seg == 0) ? out0 : (seg == 1) ? out1 : out2;
                    const int h = d >> 6;
                    const int hd = d & 63;
                    float2 w;
                    w.x = cvt_rna_tf32(v0 + bp[d + 0]);    // pre-round for flash mma
                    w.y = cvt_rna_tf32(v1 + bp[d + 1]);
                    size_t idx = ((((size_t)(b * H_NUM + h)) << 11) + s) * HD_DIM + hd;
                    *(float2*)(op + idx) = w;
                }
            }
        }
    }
}

// ===========================================================================
// Flash attention (causal) with mma.sync tf32.
// Br=Bc=64, 256 threads. S-phase: warps (wm: q-tile of 16) x (wn: kv-half of 32).
// PV-phase computes O^T = V^T * P^T so that both fragment sources (V natural
// [kv][hd], P natural [q][kv]) are K-major — no transposes.
// Pitches: Q/K/P = 68 (bank = 4*row + k, conflict-free frags),
//          V = 72 (bank = 8*k + row, conflict-free A-frags for O^T).
// K/V tiles double-buffered via cp.async.
// ===========================================================================
#define FP 68
#define VP 72
#define OFS_QS 0
#define OFS_KS (64 * FP)                 // 2 stages
#define OFS_VS (OFS_KS + 2 * 64 * FP)    // 2 stages
#define OFS_PS (OFS_VS + 2 * 64 * VP)
#define OFS_PM (OFS_PS + 64 * FP)        // pmax [2][64]
#define OFS_SU (OFS_PM + 128)            // psum [2][64]
#define OFS_FA (OFS_SU + 128)            // fac [64]
#define OFS_LS (OFS_FA + 64)             // lsm [64]
#define FLASH_FLOATS (OFS_LS + 64)       // 27008
#define FLASH_SMEM_BYTES (FLASH_FLOATS * 4)   // 108032

__global__ __launch_bounds__(256, 2) void flash_mma_kernel(
    const float* __restrict__ Q, const float* __restrict__ K,
    const float* __restrict__ V, float* __restrict__ Out)
{
    extern __shared__ float sm[];
    float* Qs   = sm + OFS_QS;
    float* Ps   = sm + OFS_PS;
    float* pmax = sm + OFS_PM;
    float* psum = sm + OFS_SU;
    float* fac  = sm + OFS_FA;
    float* lsm  = sm + OFS_LS;
    const uint32_t ks_u32 = smem_to_u32(sm + OFS_KS);
    const uint32_t vs_u32 = smem_to_u32(sm + OFS_VS);

    const int tid  = threadIdx.x;
    const int lane = tid & 31;
    const int wid  = tid >> 5;
    const int wm = wid & 3;      // q-tile (S) / hd-tile (PV)
    const int wn = wid >> 2;     // kv-half (S) / q-half (PV)
    const int fr = lane >> 2;
    const int fc = lane & 3;
    const int qb = blockIdx.x;
    const int bh = blockIdx.y;
    const int q0 = qb * 64;

    const float* Qg = Q + ((size_t)bh * S_LEN + q0) * HD_DIM;
    const float* Kg = K + (size_t)bh * S_LEN * HD_DIM;
    const float* Vg = V + (size_t)bh * S_LEN * HD_DIM;

    // load Q tile (already tf32-rounded)
    #pragma unroll
    for (int it = 0; it < 4; it++) {
        int lin = tid + it * 256;
        int row = lin >> 4;
        int c4  = (lin & 15) << 2;
        *(float4*)&Qs[row * FP + c4] = *(const float4*)&Qg[row * HD_DIM + c4];
    }

    // prologue: cp.async K/V tile 0 into buf 0
    {
        #pragma unroll
        for (int it = 0; it < 4; it++) {
            int lin = tid + it * 256;
            int row = lin >> 4;
            int c4  = (lin & 15) << 2;
            CP_ASYNC16(ks_u32 + (row * FP + c4) * 4, Kg + row * HD_DIM + c4);
            CP_ASYNC16(vs_u32 + (row * VP + c4) * 4, Vg + row * HD_DIM + c4);
        }
        CP_COMMIT();
    }

    float mI[2] = {-1e30f, -1e30f};
    float lI[2] = {0.0f, 0.0f};
    float o[4][4];
    #pragma unroll
    for (int j = 0; j < 4; j++)
        #pragma unroll
        for (int e = 0; e < 4; e++) o[j][e] = 0.0f;

    const int row0 = 16 * wm + fr;   // S-phase q rows (row0, row0+8)

    for (int t = 0; t <= qb; t++) {
        const int buf = t & 1;
        CP_WAIT0();
        __syncthreads();

        if (t < qb) {
            const float* Kt = Kg + (size_t)(t + 1) * 64 * HD_DIM;
            const float* Vt = Vg + (size_t)(t + 1) * 64 * HD_DIM;
            const uint32_t kd = ks_u32 + ((buf ^ 1) * 64 * FP) * 4;
            const uint32_t vd = vs_u32 + ((buf ^ 1) * 64 * VP) * 4;
            #pragma unroll
            for (int it = 0; it < 4; it++) {
                int lin = tid + it * 256;
                int row = lin >> 4;
                int c4  = (lin & 15) << 2;
                CP_ASYNC16(kd + (row * FP + c4) * 4, Kt + row * HD_DIM + c4);
                CP_ASYNC16(vd + (row * VP + c4) * 4, Vt + row * HD_DIM + c4);
            }
            CP_COMMIT();
        }

        // ---- S = Q K^T on warp's 16 q-rows x 32 kv-cols ----
        const float* Kb = sm + OFS_KS + buf * 64 * FP;
        float s[4][4];
        #pragma unroll
        for (int j = 0; j < 4; j++)
            #pragma unroll
            for (int e = 0; e < 4; e++) s[j][e] = 0.0f;

        #pragma unroll
        for (int kc = 0; kc < 8; kc++) {
            const int k8 = kc << 3;
            uint32_t a[4];
            a[0] = __float_as_uint(Qs[(row0)     * FP + k8 + fc]);
            a[1] = __float_as_uint(Qs[(row0 + 8) * FP + k8 + fc]);
            a[2] = __float_as_uint(Qs[(row0)     * FP + k8 + fc + 4]);
            a[3] = __float_as_uint(Qs[(row0 + 8) * FP + k8 + fc + 4]);
            #pragma unroll
            for (int j = 0; j < 4; j++) {
                const int n0 = 32 * wn + 8 * j;
                uint32_t b[2];
                b[0] = __float_as_uint(Kb[(n0 + fr) * FP + k8 + fc]);
                b[1] = __float_as_uint(Kb[(n0 + fr) * FP + k8 + fc + 4]);
                mma_tf32(s[j], a, b);
            }
        }

        // ---- scale + causal mask ----
        const bool diag = (t == qb);
        #pragma unroll
        for (int j = 0; j < 4; j++)
            #pragma unroll
            for (int e = 0; e < 4; e++) {
                float v = s[j][e] * 0.125f;
                if (diag) {
                    int col = 32 * wn + 8 * j + 2 * fc + (e & 1);
                    int row = row0 + 8 * (e >> 1);
                    if (col > row) v = -1e30f;
                }
                s[j][e] = v;
            }

        // ---- partial row max (over this warp's 32 cols) ----
        float pm[2];
        #pragma unroll
        for (int h = 0; h < 2; h++) {
            float v = fmaxf(s[0][2 * h], s[0][2 * h + 1]);
            #pragma unroll
            for (int j = 1; j < 4; j++)
                v = fmaxf(v, fmaxf(s[j][2 * h], s[j][2 * h + 1]));
            v = fmaxf(v, __shfl_xor_sync(0xffffffffu, v, 1));
            v = fmaxf(v, __shfl_xor_sync(0xffffffffu, v, 2));
            pm[h] = v;
        }
        if ((lane & 3) == 0) {
            pmax[wn * 64 + row0] = pm[0];
            pmax[wn * 64 + row0 + 8] = pm[1];
        }
        __syncthreads();

        // ---- global max, exp, P store, partial sums ----
        float facr[2], mnew[2];
        #pragma unroll
        for (int h = 0; h < 2; h++) {
            int row = row0 + 8 * h;
            mnew[h] = fmaxf(mI[h], fmaxf(pmax[row], pmax[64 + row]));
            facr[h] = __expf(mI[h] - mnew[h]);
            mI[h] = mnew[h];
        }
        float rs[2] = {0.0f, 0.0f};
        #pragma unroll
        for (int h = 0; h < 2; h++) {
            int row = row0 + 8 * h;
            #pragma unroll
            for (int j = 0; j < 4; j++) {
                float p0 = __expf(s[j][2 * h] - mnew[h]);
                float p1 = __expf(s[j][2 * h + 1] - mnew[h]);
                rs[h] += p0 + p1;
                float2 pc;
                pc.x = cvt_rna_tf32(p0);
                pc.y = cvt_rna_tf32(p1);
                *(float2*)&Ps[row * FP + 32 * wn + 8 * j + 2 * fc] = pc;
            }
            rs[h] += __shfl_xor_sync(0xffffffffu, rs[h], 1);
            rs[h] += __shfl_xor_sync(0xffffffffu, rs[h], 2);
        }
        if ((lane & 3) == 0) {
            psum[wn * 64 + row0] = rs[0];
            psum[wn * 64 + row0 + 8] = rs[1];
            if (wn == 0) {
                fac[row0] = facr[0];
                fac[row0 + 8] = facr[1];
            }
        }
        __syncthreads();

        #pragma unroll
        for (int h = 0; h < 2; h++) {
            int row = row0 + 8 * h;
            lI[h] = lI[h] * facr[h] + psum[row] + psum[64 + row];
        }

        // ---- O^T += V^T P^T  (warp: hd-tile wm x q-cols 32*wn..+31) ----
        #pragma unroll
        for (int j = 0; j < 4; j++) {
            float f0 = fac[32 * wn + 8 * j + 2 * fc];
            float f1 = fac[32 * wn + 8 * j + 2 * fc + 1];
            o[j][0] *= f0; o[j][1] *= f1; o[j][2] *= f0; o[j][3] *= f1;
        }
        const float* Vb = sm + OFS_VS + buf * 64 * VP;
        #pragma unroll
        for (int kc = 0; kc < 8; kc++) {
            const int k8 = kc << 3;
            uint32_t a[4];
            a[0] = __float_as_uint(Vb[(k8 + fc)     * VP + row0]);
            a[1] = __float_as_uint(Vb[(k8 + fc)     * VP + row0 + 8]);
            a[2] = __float_as_uint(Vb[(k8 + fc + 4) * VP + row0]);
            a[3] = __float_as_uint(Vb[(k8 + fc + 4) * VP + row0 + 8]);
            #pragma unroll
            for (int j = 0; j < 4; j++) {
                const int n0 = 32 * wn + 8 * j;
                uint32_t b[2];
                b[0] = __float_as_uint(Ps[(n0 + fr) * FP + k8 + fc]);
                b[1] = __float_as_uint(Ps[(n0 + fr) * FP + k8 + fc + 4]);
                mma_tf32(o[j], a, b);
            }
        }
    }

    if (wn == 0 && (lane & 3) == 0) {
        lsm[row0] = lI[0];
        lsm[row0 + 8] = lI[1];
    }
    __syncthreads();

    // ---- epilogue: Out[b][q0+q][h*64+hd] = cvt(o / l) ----
    const int b = bh >> 4;
    const int h = bh & 15;
    #pragma unroll
    for (int j = 0; j < 4; j++) {
        const int q = 32 * wn + 8 * j + 2 * fc;
        const float inv0 = 1.0f / lsm[q];
        const float inv1 = 1.0f / lsm[q + 1];
        const int hd = 16 * wm + fr;
        size_t base0 = ((size_t)(b * S_LEN + q0 + q)) * D_DIM + h * HD_DIM;
        size_t base1 = base0 + D_DIM;
        Out[base0 + hd]     = cvt_rna_tf32(o[j][0] * inv0);
        Out[base1 + hd]     = cvt_rna_tf32(o[j][1] * inv1);
        Out[base0 + hd + 8] = cvt_rna_tf32(o[j][2] * inv0);
        Out[base1 + hd + 8] = cvt_rna_tf32(o[j][3] * inv1);
    }
}

// ---------------------------------------------------------------------------
// Launch
// ---------------------------------------------------------------------------
extern "C" void kernel_launch(void* const* d_in, const int* in_sizes, int n_in,
                              void* d_out, int out_size)
{
    const float* x  = (const float*)d_in[0];
    // d_in[1] = mask — reproduced analytically in-kernel
    const float* wq = (const float*)d_in[2];
    const float* bq = (const float*)d_in[3];
    const float* wk = (const float*)d_in[4];
    const float* bk = (const float*)d_in[5];
    const float* wv = (const float*)d_in[6];
    const float* bv = (const float*)d_in[7];
    const float* wo = (const float*)d_in[8];
    const float* bo = (const float*)d_in[9];
    float* out = (float*)d_out;

    float *Qp, *Kp, *Vp, *Cp, *xcp, *wtp;
    cudaGetSymbolAddress((void**)&Qp, g_Q);
    cudaGetSymbolAddress((void**)&Kp, g_K);
    cudaGetSymbolAddress((void**)&Vp, g_V);
    cudaGetSymbolAddress((void**)&Cp, g_Ctx);
    cudaGetSymbolAddress((void**)&xcp, g_xc);
    cudaGetSymbolAddress((void**)&wtp, g_WT);

    cudaFuncSetAttribute(flash_mma_kernel,
                         cudaFuncAttributeMaxDynamicSharedMemorySize,
                         FLASH_SMEM_BYTES);
    cudaFuncSetAttribute(gemm_mma_kernel,
                         cudaFuncAttributeMaxDynamicSharedMemorySize,
                         GEMM_SMEM_BYTES);

    // 1. tf32-round x
    cvt_x_kernel<<<(M_TOT * D_DIM) / (4 * 256), 256>>>(x, xcp);

    // 2. transpose + tf32-round weights (Wq|Wk|Wv|Wo -> WT[n][k])
    transpose_w_kernel<<<dim3(D_DIM / 32, (4 * D_DIM) / 32), 256>>>(wq, wk, wv, wo, wtp);

    // 3. fused QKV projection (N=3072), head-split + tf32-round epilogue
    gemm_mma_kernel<<<dim3(N_QKV / 128, M_TOT / 128), 256, GEMM_SMEM_BYTES>>>(
        xcp, wtp, bq, bk, bv, Qp, Kp, Vp, 1);

    // 4. attention (tensor-core flash)
    flash_mma_kernel<<<dim3(S_LEN / 64, B_NUM * H_NUM), 256, FLASH_SMEM_BYTES>>>(
        Qp, Kp, Vp, Cp);

    // 5. output projection
    gemm_mma_kernel<<<dim3(D_DIM / 128, M_TOT / 128), 256, GEMM_SMEM_BYTES>>>(
        Cp, wtp + (size_t)3 * D_DIM * D_DIM, bo, bo, bo, out, out, out, 0);
}